// round 8
// baseline (speedup 1.0000x reference)
#include <cuda_runtime.h>
#include <cuda_bf16.h>
#include <mma.h>

using namespace nvcuda;

// Problem constants
constexpr int T_ = 4;
constexpr int B_ = 16;
constexpr int C_ = 512;
constexpr int N_ = 256;                // H*W
constexpr int S_ = B_ * C_ * N_;       // per-timestep elements
constexpr int TOT_ = T_ * S_;

// GEMM tiling
constexpr int BM = 128, BN = 64, BK = 32;
constexpr int ASTR = 36;   // fp32, row bytes 144 (16B multiple)
constexpr int BSTR = 68;   // fp32, row bytes 272 (16B multiple)
constexpr int CSTR = 68;
constexpr int SMEM_BYTES = (2 * BM * ASTR + 2 * BK * BSTR) * 4;  // 54272

// Scratch (device globals: allocation-free rule)
__device__ __align__(16) float g_wq[C_ * C_];
__device__ __align__(16) float g_wk[C_ * C_];
__device__ __align__(16) float g_wv[C_ * C_];
__device__ __align__(16) float g_wp[C_ * C_];
__device__ float g_sq[C_];
__device__ float g_sk[C_];
__device__ float g_sv[C_];
__device__ float g_sp[C_];
__device__ __align__(16) float g_xs[TOT_];
__device__ __align__(16) float g_q[TOT_];
__device__ __align__(16) float g_k[TOT_];
__device__ __align__(16) float g_v[TOT_];
__device__ float g_kvs[T_ * B_ * C_];

// ---------------------------------------------------------------------------
// cp.async helpers
// ---------------------------------------------------------------------------
__device__ __forceinline__ void cp16(void* dst, const void* src) {
    unsigned s = (unsigned)__cvta_generic_to_shared(dst);
    asm volatile("cp.async.cg.shared.global [%0], [%1], 16;\n" :: "r"(s), "l"(src));
}
__device__ __forceinline__ void cp16p(void* dst, const void* src, int srcsize) {
    unsigned s = (unsigned)__cvta_generic_to_shared(dst);
    asm volatile("cp.async.cg.shared.global [%0], [%1], 16, %2;\n" :: "r"(s), "l"(src), "r"(srcsize));
}
#define CP_COMMIT() asm volatile("cp.async.commit_group;\n" ::: "memory")
#define CP_WAIT0()  asm volatile("cp.async.wait_group 0;\n" ::: "memory")

// ---------------------------------------------------------------------------
// Prep: fold BN scale into weights; compute per-channel shifts.
// ---------------------------------------------------------------------------
__global__ void prep_kernel(
    const float* __restrict__ qw, const float* __restrict__ qg, const float* __restrict__ qb,
    const float* __restrict__ qm, const float* __restrict__ qvv,
    const float* __restrict__ kw, const float* __restrict__ kg, const float* __restrict__ kb,
    const float* __restrict__ km, const float* __restrict__ kvv,
    const float* __restrict__ vw, const float* __restrict__ vg, const float* __restrict__ vb,
    const float* __restrict__ vm, const float* __restrict__ vvv,
    const float* __restrict__ pw, const float* __restrict__ pb, const float* __restrict__ pg,
    const float* __restrict__ pb2, const float* __restrict__ pm, const float* __restrict__ pvv)
{
    int idx = blockIdx.x * blockDim.x + threadIdx.x;
    if (idx >= C_ * C_) return;
    int o = idx >> 9;
    float invq = qg[o] / sqrtf(qvv[o] + 1e-5f);
    float invk = kg[o] / sqrtf(kvv[o] + 1e-5f);
    float invv = vg[o] / sqrtf(vvv[o] + 1e-5f);
    float invp = pg[o] / sqrtf(pvv[o] + 1e-5f);
    g_wq[idx] = qw[idx] * invq;
    g_wk[idx] = kw[idx] * invk;
    g_wv[idx] = vw[idx] * invv;
    g_wp[idx] = pw[idx] * invp;
    if ((idx & 511) == 0) {
        g_sq[o] = qb[o] - qm[o] * invq;
        g_sk[o] = kb[o] - km[o] * invk;
        g_sv[o] = vb[o] - vm[o] * invv;
        g_sp[o] = (pb[o] - pm[o]) * invp + pb2[o];
    }
}

// ---------------------------------------------------------------------------
// LIF on input x -> binary spikes xs.
// ---------------------------------------------------------------------------
__global__ void lif_x_kernel(const float* __restrict__ x)
{
    int i = blockIdx.x * blockDim.x + threadIdx.x;
    if (i >= S_) return;
    float v = 0.f;
#pragma unroll
    for (int t = 0; t < T_; t++) {
        float xv = x[t * S_ + i];
        v = v + (xv - v) * 0.5f;
        float s = (v >= 1.0f) ? 1.f : 0.f;
        g_xs[t * S_ + i] = s;
        v = v * (1.f - s);
    }
}

// ---------------------------------------------------------------------------
// kv = sum_n k*v per (t,b,c), then LIF with v_th=0.5.
// ---------------------------------------------------------------------------
__global__ void kv_kernel()
{
    int gw = (blockIdx.x * blockDim.x + threadIdx.x) >> 5;
    int lane = threadIdx.x & 31;
    if (gw >= B_ * C_) return;      // gw = b*C + c
    float v = 0.f;
#pragma unroll
    for (int t = 0; t < T_; t++) {
        const float* kp = g_k + t * S_ + gw * N_;
        const float* vp = g_v + t * S_ + gw * N_;
        float sum = 0.f;
#pragma unroll
        for (int j = 0; j < N_ / 32; j++)
            sum += kp[lane + j * 32] * vp[lane + j * 32];
#pragma unroll
        for (int off = 16; off > 0; off >>= 1)
            sum += __shfl_xor_sync(0xFFFFFFFFu, sum, off);
        v = v + (sum - v) * 0.5f;
        float s = (v >= 0.5f) ? 1.f : 0.f;
        if (lane == 0) g_kvs[t * B_ * C_ + gw] = s;
        v = v * (1.f - s);
    }
}

// ---------------------------------------------------------------------------
// Pipelined tf32 GEMM, 128x64x32 tiles, cp.async double buffered.
// MODE 0: z = which*16 + b. Loops t=0..3 internally; A = folded weights,
//         B = xs spikes; epilogue applies BN shift + LIF (v carried in regs),
//         writes binary spikes to g_q/g_k/g_v.
// MODE 1: z = tb (t*B + b). A = proj weights, B = q spikes gated by kvs via
//         zero-fill cp.async; epilogue adds shift + identity, writes d_out.
// ---------------------------------------------------------------------------
template <int MODE>
__global__ void __launch_bounds__(256) gemm_kernel(const float* __restrict__ x_identity,
                                                   float* __restrict__ out_global)
{
    extern __shared__ float smem[];
    float* AsBase = smem;                      // [2][BM*ASTR]
    float* BsBase = smem + 2 * BM * ASTR;      // [2][BK*BSTR]
    float* Cs = smem;                          // overlaps As (used after syncs)

    int tid = threadIdx.x;
    int warp = tid >> 5;
    int wr = warp >> 1, wc = warp & 1;
    int n0 = blockIdx.x * BN;
    int o0 = blockIdx.y * BM;
    int z = blockIdx.z;

    const float* A;
    const float* shp;
    float* Cdst0 = nullptr;      // MODE 0 spike output base (t=0)
    const float* Bsrc0;
    const float* kvs = nullptr;
    const float* xid = nullptr;
    float* outp = nullptr;

    if (MODE == 0) {
        int which = z >> 4;
        int b = z & 15;
        A = (which == 0) ? g_wq : (which == 1) ? g_wk : g_wv;
        shp = (which == 0) ? g_sq : (which == 1) ? g_sk : g_sv;
        Bsrc0 = g_xs + (size_t)b * C_ * N_;
        Cdst0 = ((which == 0) ? g_q : (which == 1) ? g_k : g_v) + (size_t)b * C_ * N_;
    } else {
        A = g_wp;
        shp = g_sp;
        Bsrc0 = g_q + (size_t)z * C_ * N_;
        kvs = g_kvs + z * C_;
        xid = x_identity + (size_t)z * C_ * N_;
        outp = out_global + (size_t)z * C_ * N_;
    }

    // Per-thread epilogue element map: idx = tid + e*256 -> r = idx>>6, c = idx&63
    float vmem[32];
    if (MODE == 0) {
#pragma unroll
        for (int e = 0; e < 32; e++) vmem[e] = 0.f;
    }

    const int TLOOP = (MODE == 0) ? T_ : 1;

    for (int t = 0; t < TLOOP; t++) {
        const float* Bsrc = Bsrc0 + (size_t)t * S_;   // S_ stride only used MODE 0
        float* Cdst = (MODE == 0) ? (Cdst0 + (size_t)t * S_) : nullptr;

        wmma::fragment<wmma::accumulator, 16, 16, 8, float> acc[2][2];
#pragma unroll
        for (int i = 0; i < 2; i++)
#pragma unroll
            for (int j = 0; j < 2; j++)
                wmma::fill_fragment(acc[i][j], 0.0f);

        // ---- prologue: issue chunk 0 into buffer 0
        {
            float* As = AsBase;
            float* Bs = BsBase;
#pragma unroll
            for (int i = 0; i < 4; i++) {
                int idx = tid + i * 256;
                int r = idx >> 3, c4 = (idx & 7) << 2;
                cp16(&As[r * ASTR + c4], &A[(o0 + r) * C_ + c4]);
            }
#pragma unroll
            for (int i = 0; i < 2; i++) {
                int idx = tid + i * 256;
                int r = idx >> 4, c4 = (idx & 15) << 2;
                if (MODE == 0) {
                    cp16(&Bs[r * BSTR + c4], &Bsrc[r * N_ + n0 + c4]);
                } else {
                    int sz = (__ldg(&kvs[r]) != 0.f) ? 16 : 0;
                    cp16p(&Bs[r * BSTR + c4], &Bsrc[r * N_ + n0 + c4], sz);
                }
            }
            CP_COMMIT();
        }

        // ---- main K loop
        int s = 0;
        for (int kt = 0; kt < C_; kt += BK, s ^= 1) {
            CP_WAIT0();
            __syncthreads();

            if (kt + BK < C_) {
                float* As = AsBase + (s ^ 1) * BM * ASTR;
                float* Bs = BsBase + (s ^ 1) * BK * BSTR;
                int ktn = kt + BK;
#pragma unroll
                for (int i = 0; i < 4; i++) {
                    int idx = tid + i * 256;
                    int r = idx >> 3, c4 = (idx & 7) << 2;
                    cp16(&As[r * ASTR + c4], &A[(o0 + r) * C_ + ktn + c4]);
                }
#pragma unroll
                for (int i = 0; i < 2; i++) {
                    int idx = tid + i * 256;
                    int r = idx >> 4, c4 = (idx & 15) << 2;
                    if (MODE == 0) {
                        cp16(&Bs[r * BSTR + c4], &Bsrc[(ktn + r) * N_ + n0 + c4]);
                    } else {
                        int sz = (__ldg(&kvs[ktn + r]) != 0.f) ? 16 : 0;
                        cp16p(&Bs[r * BSTR + c4], &Bsrc[(ktn + r) * N_ + n0 + c4], sz);
                    }
                }
                CP_COMMIT();
            }

            const float* As = AsBase + s * BM * ASTR;
            const float* Bs = BsBase + s * BK * BSTR;
#pragma unroll
            for (int kk = 0; kk < BK; kk += 8) {
                wmma::fragment<wmma::matrix_a, 16, 16, 8, wmma::precision::tf32, wmma::row_major> af[2];
                wmma::fragment<wmma::matrix_b, 16, 16, 8, wmma::precision::tf32, wmma::row_major> bf[2];
#pragma unroll
                for (int i = 0; i < 2; i++) {
                    wmma::load_matrix_sync(af[i], &As[(wr * 32 + i * 16) * ASTR + kk], ASTR);
#pragma unroll
                    for (int e = 0; e < af[i].num_elements; e++)
                        af[i].x[e] = wmma::__float_to_tf32(af[i].x[e]);
                }
#pragma unroll
                for (int j = 0; j < 2; j++) {
                    wmma::load_matrix_sync(bf[j], &Bs[kk * BSTR + wc * 32 + j * 16], BSTR);
#pragma unroll
                    for (int e = 0; e < bf[j].num_elements; e++)
                        bf[j].x[e] = wmma::__float_to_tf32(bf[j].x[e]);
                }
#pragma unroll
                for (int i = 0; i < 2; i++)
#pragma unroll
                    for (int j = 0; j < 2; j++)
                        wmma::mma_sync(acc[i][j], af[i], bf[j], acc[i][j]);
            }
        }

        // ---- epilogue: stage accumulator tile in smem (overlaps A/B buffers)
        __syncthreads();   // all mma reads done before Cs overwrite
#pragma unroll
        for (int i = 0; i < 2; i++)
#pragma unroll
            for (int j = 0; j < 2; j++)
                wmma::store_matrix_sync(&Cs[(wr * 32 + i * 16) * CSTR + wc * 32 + j * 16],
                                        acc[i][j], CSTR, wmma::mem_row_major);
        __syncthreads();

        if (MODE == 0) {
#pragma unroll
            for (int e = 0; e < 32; e++) {
                int idx = tid + e * 256;
                int r = idx >> 6, c = idx & 63;
                float pre = Cs[r * CSTR + c] + __ldg(&shp[o0 + r]);
                float v = vmem[e];
                v = v + (pre - v) * 0.5f;
                float sp = (v >= 1.0f) ? 1.f : 0.f;
                vmem[e] = v * (1.f - sp);
                Cdst[(o0 + r) * N_ + n0 + c] = sp;
            }
        } else {
#pragma unroll
            for (int e = 0; e < 32; e++) {
                int idx = tid + e * 256;
                int r = idx >> 6, c = idx & 63;
                int o = o0 + r;
                float val = Cs[r * CSTR + c] + __ldg(&shp[o]) + xid[o * N_ + n0 + c];
                outp[o * N_ + n0 + c] = val;
            }
        }
        __syncthreads();   // protect Cs before next t's prologue overwrites
    }
}

// ---------------------------------------------------------------------------
extern "C" void kernel_launch(void* const* d_in, const int* in_sizes, int n_in,
                              void* d_out, int out_size)
{
    const float* x    = (const float*)d_in[0];
    const float* q_w  = (const float*)d_in[1];
    const float* q_g  = (const float*)d_in[2];
    const float* q_b  = (const float*)d_in[3];
    const float* q_m  = (const float*)d_in[4];
    const float* q_v  = (const float*)d_in[5];
    const float* k_w  = (const float*)d_in[6];
    const float* k_g  = (const float*)d_in[7];
    const float* k_b  = (const float*)d_in[8];
    const float* k_m  = (const float*)d_in[9];
    const float* k_v  = (const float*)d_in[10];
    const float* v_w  = (const float*)d_in[11];
    const float* v_g  = (const float*)d_in[12];
    const float* v_b  = (const float*)d_in[13];
    const float* v_m  = (const float*)d_in[14];
    const float* v_v  = (const float*)d_in[15];
    const float* p_w  = (const float*)d_in[16];
    const float* p_b  = (const float*)d_in[17];
    const float* p_g  = (const float*)d_in[18];
    const float* p_b2 = (const float*)d_in[19];
    const float* p_m  = (const float*)d_in[20];
    const float* p_v  = (const float*)d_in[21];
    float* out = (float*)d_out;

    cudaFuncSetAttribute(gemm_kernel<0>, cudaFuncAttributeMaxDynamicSharedMemorySize, SMEM_BYTES);
    cudaFuncSetAttribute(gemm_kernel<1>, cudaFuncAttributeMaxDynamicSharedMemorySize, SMEM_BYTES);

    prep_kernel<<<(C_ * C_ + 255) / 256, 256>>>(
        q_w, q_g, q_b, q_m, q_v,
        k_w, k_g, k_b, k_m, k_v,
        v_w, v_g, v_b, v_m, v_v,
        p_w, p_b, p_g, p_b2, p_m, p_v);

    lif_x_kernel<<<(S_ + 255) / 256, 256>>>(x);

    // MODE 0: q/k/v convs + fused BN shift + LIF (t looped in-kernel)
    gemm_kernel<0><<<dim3(N_ / BN, C_ / BM, 3 * B_), 256, SMEM_BYTES>>>(nullptr, nullptr);

    kv_kernel<<<(B_ * C_ * 32 + 255) / 256, 256>>>();

    // MODE 1: proj conv on q*kvs + BN + bias + identity
    gemm_kernel<1><<<dim3(N_ / BN, C_ / BM, T_ * B_), 256, SMEM_BYTES>>>(x, out);
}

// round 9
// speedup vs baseline: 1.3859x; 1.3859x over previous
#include <cuda_runtime.h>
#include <cuda_bf16.h>
#include <mma.h>

using namespace nvcuda;

// Problem constants
constexpr int T_ = 4;
constexpr int B_ = 16;
constexpr int C_ = 512;
constexpr int N_ = 256;                // H*W
constexpr int S_ = B_ * C_ * N_;       // per-timestep elements
constexpr int TOT_ = T_ * S_;

// GEMM tiling: block 128x128x32, 4 warps, warp tile 64x64
constexpr int BM = 128, BN = 128, BK = 32;
constexpr int ASTR = 36;    // row stride floats; 144B = 9*16 (cp.async 16B aligned)
constexpr int BSTR = 132;   // 528B = 33*16
constexpr int CSTR = 132;
constexpr int SMEM_BYTES = 2 * (BM * ASTR + BK * BSTR) * 4;   // 70656

// Scratch (device globals: allocation-free rule)
__device__ __align__(16) float g_wq[C_ * C_];
__device__ __align__(16) float g_wk[C_ * C_];
__device__ __align__(16) float g_wv[C_ * C_];
__device__ __align__(16) float g_wp[C_ * C_];
__device__ float g_sq[C_];
__device__ float g_sk[C_];
__device__ float g_sv[C_];
__device__ float g_sp[C_];
__device__ __align__(16) float g_xs[TOT_];
__device__ __align__(16) float g_q[TOT_];
__device__ __align__(16) float g_k[TOT_];
__device__ __align__(16) float g_v[TOT_];
__device__ float g_kvs[T_ * B_ * C_];

// ---------------------------------------------------------------------------
// cp.async helpers
// ---------------------------------------------------------------------------
__device__ __forceinline__ void cp16(void* dst, const void* src) {
    unsigned s = (unsigned)__cvta_generic_to_shared(dst);
    asm volatile("cp.async.cg.shared.global [%0], [%1], 16;\n" :: "r"(s), "l"(src));
}
__device__ __forceinline__ void cp16p(void* dst, const void* src, int srcsize) {
    unsigned s = (unsigned)__cvta_generic_to_shared(dst);
    asm volatile("cp.async.cg.shared.global [%0], [%1], 16, %2;\n" :: "r"(s), "l"(src), "r"(srcsize));
}
#define CP_COMMIT() asm volatile("cp.async.commit_group;\n" ::: "memory")
#define CP_WAIT0()  asm volatile("cp.async.wait_group 0;\n" ::: "memory")

// ---------------------------------------------------------------------------
// Prep: fold BN scale into weights; compute per-channel shifts.
// ---------------------------------------------------------------------------
__global__ void prep_kernel(
    const float* __restrict__ qw, const float* __restrict__ qg, const float* __restrict__ qb,
    const float* __restrict__ qm, const float* __restrict__ qvv,
    const float* __restrict__ kw, const float* __restrict__ kg, const float* __restrict__ kb,
    const float* __restrict__ km, const float* __restrict__ kvv,
    const float* __restrict__ vw, const float* __restrict__ vg, const float* __restrict__ vb,
    const float* __restrict__ vm, const float* __restrict__ vvv,
    const float* __restrict__ pw, const float* __restrict__ pb, const float* __restrict__ pg,
    const float* __restrict__ pb2, const float* __restrict__ pm, const float* __restrict__ pvv)
{
    int idx = blockIdx.x * blockDim.x + threadIdx.x;
    if (idx >= C_ * C_) return;
    int o = idx >> 9;
    float invq = qg[o] / sqrtf(qvv[o] + 1e-5f);
    float invk = kg[o] / sqrtf(kvv[o] + 1e-5f);
    float invv = vg[o] / sqrtf(vvv[o] + 1e-5f);
    float invp = pg[o] / sqrtf(pvv[o] + 1e-5f);
    g_wq[idx] = qw[idx] * invq;
    g_wk[idx] = kw[idx] * invk;
    g_wv[idx] = vw[idx] * invv;
    g_wp[idx] = pw[idx] * invp;
    if ((idx & 511) == 0) {
        g_sq[o] = qb[o] - qm[o] * invq;
        g_sk[o] = kb[o] - km[o] * invk;
        g_sv[o] = vb[o] - vm[o] * invv;
        g_sp[o] = (pb[o] - pm[o]) * invp + pb2[o];
    }
}

// ---------------------------------------------------------------------------
// LIF on input x -> binary spikes xs (float4 vectorized).
// ---------------------------------------------------------------------------
__global__ void lif_x_kernel(const float4* __restrict__ x4)
{
    int i = blockIdx.x * blockDim.x + threadIdx.x;
    if (i >= S_ / 4) return;
    float4* xs4 = reinterpret_cast<float4*>(g_xs);
    float4 v = make_float4(0.f, 0.f, 0.f, 0.f);
#pragma unroll
    for (int t = 0; t < T_; t++) {
        float4 xv = x4[t * (S_ / 4) + i];
        float4 s;
        v.x += (xv.x - v.x) * 0.5f; s.x = (v.x >= 1.f) ? 1.f : 0.f; v.x *= (1.f - s.x);
        v.y += (xv.y - v.y) * 0.5f; s.y = (v.y >= 1.f) ? 1.f : 0.f; v.y *= (1.f - s.y);
        v.z += (xv.z - v.z) * 0.5f; s.z = (v.z >= 1.f) ? 1.f : 0.f; v.z *= (1.f - s.z);
        v.w += (xv.w - v.w) * 0.5f; s.w = (v.w >= 1.f) ? 1.f : 0.f; v.w *= (1.f - s.w);
        xs4[t * (S_ / 4) + i] = s;
    }
}

// ---------------------------------------------------------------------------
// LIF on q/k/v pre-activations (+ BN shift), in place -> spikes (float4).
// ---------------------------------------------------------------------------
__global__ void lif_qkv_kernel()
{
    int i = blockIdx.x * blockDim.x + threadIdx.x;
    if (i >= S_ / 4) return;
    int which = blockIdx.y;
    float4* buf = reinterpret_cast<float4*>((which == 0) ? g_q : (which == 1) ? g_k : g_v);
    const float* sh = (which == 0) ? g_sq : (which == 1) ? g_sk : g_sv;
    int c = (i >> 6) & (C_ - 1);    // i indexes [b][c][n/4], 64 float4 per row
    float shift = __ldg(&sh[c]);
    float4 v = make_float4(0.f, 0.f, 0.f, 0.f);
#pragma unroll
    for (int t = 0; t < T_; t++) {
        float4 p = buf[t * (S_ / 4) + i];
        p.x += shift; p.y += shift; p.z += shift; p.w += shift;
        float4 s;
        v.x += (p.x - v.x) * 0.5f; s.x = (v.x >= 1.f) ? 1.f : 0.f; v.x *= (1.f - s.x);
        v.y += (p.y - v.y) * 0.5f; s.y = (v.y >= 1.f) ? 1.f : 0.f; v.y *= (1.f - s.y);
        v.z += (p.z - v.z) * 0.5f; s.z = (v.z >= 1.f) ? 1.f : 0.f; v.z *= (1.f - s.z);
        v.w += (p.w - v.w) * 0.5f; s.w = (v.w >= 1.f) ? 1.f : 0.f; v.w *= (1.f - s.w);
        buf[t * (S_ / 4) + i] = s;
    }
}

// ---------------------------------------------------------------------------
// kv = sum_n k*v per (t,b,c), then LIF with v_th=0.5.
// ---------------------------------------------------------------------------
__global__ void kv_kernel()
{
    int gw = (blockIdx.x * blockDim.x + threadIdx.x) >> 5;
    int lane = threadIdx.x & 31;
    if (gw >= B_ * C_) return;      // gw = b*C + c
    float v = 0.f;
#pragma unroll
    for (int t = 0; t < T_; t++) {
        const float4* kp = reinterpret_cast<const float4*>(g_k + t * S_ + gw * N_);
        const float4* vp = reinterpret_cast<const float4*>(g_v + t * S_ + gw * N_);
        float sum = 0.f;
#pragma unroll
        for (int j = 0; j < 2; j++) {
            float4 a = kp[lane + 32 * j];
            float4 b = vp[lane + 32 * j];
            sum += a.x * b.x + a.y * b.y + a.z * b.z + a.w * b.w;
        }
#pragma unroll
        for (int off = 16; off > 0; off >>= 1)
            sum += __shfl_xor_sync(0xFFFFFFFFu, sum, off);
        v = v + (sum - v) * 0.5f;
        float s = (v >= 0.5f) ? 1.f : 0.f;
        if (lane == 0) g_kvs[t * B_ * C_ + gw] = s;
        v = v * (1.f - s);
    }
}

// ---------------------------------------------------------------------------
// tf32 GEMM, block 128x128x32, 4 warps (warp tile 64x64), 2-stage cp.async.
// MODE 0: z = which*64 + tb.  A = folded weights, B = xs spikes,
//         writes raw pre-activations to g_q/g_k/g_v (staged, coalesced).
// MODE 1: z = tb. A = proj weights, B = q spikes gated by kvs (zero-fill
//         cp.async); epilogue adds shift + identity, writes d_out.
// ---------------------------------------------------------------------------
template <int MODE>
__global__ void __launch_bounds__(128) gemm_kernel(const float* __restrict__ x_identity,
                                                   float* __restrict__ out_global)
{
    extern __shared__ float smem[];
    float* AsBase = smem;                      // [2][BM*ASTR]
    float* BsBase = smem + 2 * BM * ASTR;      // [2][BK*BSTR]
    float* Cs = smem;                          // overlaps (after sync)

    int tid = threadIdx.x;
    int warp = tid >> 5;
    int wr = warp >> 1, wc = warp & 1;         // warp tile origin: (wr*64, wc*64)
    int n0 = blockIdx.x * BN;
    int o0 = blockIdx.y * BM;
    int z = blockIdx.z;

    const float* A;
    const float* Bsrc;
    float* Cdst = nullptr;
    const float* kvs = nullptr;
    const float* xid = nullptr;
    float* outp = nullptr;
    const float* shp = nullptr;

    if (MODE == 0) {
        int which = z >> 6;
        int tb = z & 63;
        A = (which == 0) ? g_wq : (which == 1) ? g_wk : g_wv;
        Bsrc = g_xs + (size_t)tb * C_ * N_;
        Cdst = ((which == 0) ? g_q : (which == 1) ? g_k : g_v) + (size_t)tb * C_ * N_;
    } else {
        A = g_wp;
        shp = g_sp;
        Bsrc = g_q + (size_t)z * C_ * N_;
        kvs = g_kvs + z * C_;
        xid = x_identity + (size_t)z * C_ * N_;
        outp = out_global + (size_t)z * C_ * N_;
    }

    wmma::fragment<wmma::accumulator, 16, 16, 8, float> acc[4][4];
#pragma unroll
    for (int i = 0; i < 4; i++)
#pragma unroll
        for (int j = 0; j < 4; j++)
            wmma::fill_fragment(acc[i][j], 0.0f);

    // ---- prologue: issue chunk 0 into buffer 0
    {
        float* As = AsBase;
        float* Bs = BsBase;
#pragma unroll
        for (int i = 0; i < 8; i++) {               // A: 128x32 = 1024 float4
            int idx = tid + i * 128;
            int r = idx >> 3, c4 = (idx & 7) << 2;
            cp16(&As[r * ASTR + c4], &A[(o0 + r) * C_ + c4]);
        }
#pragma unroll
        for (int i = 0; i < 8; i++) {               // B: 32x128 = 1024 float4
            int idx = tid + i * 128;
            int r = idx >> 5, c4 = (idx & 31) << 2;
            if (MODE == 0) {
                cp16(&Bs[r * BSTR + c4], &Bsrc[r * N_ + n0 + c4]);
            } else {
                int sz = (__ldg(&kvs[r]) != 0.f) ? 16 : 0;
                cp16p(&Bs[r * BSTR + c4], &Bsrc[r * N_ + n0 + c4], sz);
            }
        }
        CP_COMMIT();
    }

    // ---- main K loop
    int s = 0;
    for (int kt = 0; kt < C_; kt += BK, s ^= 1) {
        CP_WAIT0();
        __syncthreads();

        if (kt + BK < C_) {
            float* As = AsBase + (s ^ 1) * BM * ASTR;
            float* Bs = BsBase + (s ^ 1) * BK * BSTR;
            int ktn = kt + BK;
#pragma unroll
            for (int i = 0; i < 8; i++) {
                int idx = tid + i * 128;
                int r = idx >> 3, c4 = (idx & 7) << 2;
                cp16(&As[r * ASTR + c4], &A[(o0 + r) * C_ + ktn + c4]);
            }
#pragma unroll
            for (int i = 0; i < 8; i++) {
                int idx = tid + i * 128;
                int r = idx >> 5, c4 = (idx & 31) << 2;
                if (MODE == 0) {
                    cp16(&Bs[r * BSTR + c4], &Bsrc[(ktn + r) * N_ + n0 + c4]);
                } else {
                    int sz = (__ldg(&kvs[ktn + r]) != 0.f) ? 16 : 0;
                    cp16p(&Bs[r * BSTR + c4], &Bsrc[(ktn + r) * N_ + n0 + c4], sz);
                }
            }
            CP_COMMIT();
        }

        const float* As = AsBase + s * BM * ASTR;
        const float* Bs = BsBase + s * BK * BSTR;
#pragma unroll
        for (int kk = 0; kk < BK; kk += 8) {
            wmma::fragment<wmma::matrix_a, 16, 16, 8, wmma::precision::tf32, wmma::row_major> af[4];
            wmma::fragment<wmma::matrix_b, 16, 16, 8, wmma::precision::tf32, wmma::row_major> bf[4];
#pragma unroll
            for (int i = 0; i < 4; i++) {
                wmma::load_matrix_sync(af[i], &As[(wr * 64 + i * 16) * ASTR + kk], ASTR);
#pragma unroll
                for (int e = 0; e < af[i].num_elements; e++)
                    af[i].x[e] = wmma::__float_to_tf32(af[i].x[e]);
            }
#pragma unroll
            for (int j = 0; j < 4; j++) {
                wmma::load_matrix_sync(bf[j], &Bs[kk * BSTR + wc * 64 + j * 16], BSTR);
#pragma unroll
                for (int e = 0; e < bf[j].num_elements; e++)
                    bf[j].x[e] = wmma::__float_to_tf32(bf[j].x[e]);
            }
#pragma unroll
            for (int i = 0; i < 4; i++)
#pragma unroll
                for (int j = 0; j < 4; j++)
                    wmma::mma_sync(acc[i][j], af[i], bf[j], acc[i][j]);
        }
    }

    // ---- epilogue: stage through smem for coalesced float4 stores
    __syncthreads();
#pragma unroll
    for (int i = 0; i < 4; i++)
#pragma unroll
        for (int j = 0; j < 4; j++)
            wmma::store_matrix_sync(&Cs[(wr * 64 + i * 16) * CSTR + wc * 64 + j * 16],
                                    acc[i][j], CSTR, wmma::mem_row_major);
    __syncthreads();

    // 128x128 tile = 4096 float4; 32 per thread
    if (MODE == 0) {
#pragma unroll
        for (int e = 0; e < 32; e++) {
            int idx = tid + e * 128;
            int r = idx >> 5, c4 = (idx & 31) << 2;
            float4 cv = *reinterpret_cast<const float4*>(&Cs[r * CSTR + c4]);
            *reinterpret_cast<float4*>(&Cdst[(o0 + r) * N_ + n0 + c4]) = cv;
        }
    } else {
#pragma unroll
        for (int e = 0; e < 32; e++) {
            int idx = tid + e * 128;
            int r = idx >> 5, c4 = (idx & 31) << 2;
            int o = o0 + r;
            float4 cv = *reinterpret_cast<const float4*>(&Cs[r * CSTR + c4]);
            float4 xv = *reinterpret_cast<const float4*>(&xid[o * N_ + n0 + c4]);
            float sp = __ldg(&shp[o]);
            float4 res;
            res.x = cv.x + sp + xv.x;
            res.y = cv.y + sp + xv.y;
            res.z = cv.z + sp + xv.z;
            res.w = cv.w + sp + xv.w;
            *reinterpret_cast<float4*>(&outp[o * N_ + n0 + c4]) = res;
        }
    }
}

// ---------------------------------------------------------------------------
extern "C" void kernel_launch(void* const* d_in, const int* in_sizes, int n_in,
                              void* d_out, int out_size)
{
    const float* x    = (const float*)d_in[0];
    const float* q_w  = (const float*)d_in[1];
    const float* q_g  = (const float*)d_in[2];
    const float* q_b  = (const float*)d_in[3];
    const float* q_m  = (const float*)d_in[4];
    const float* q_v  = (const float*)d_in[5];
    const float* k_w  = (const float*)d_in[6];
    const float* k_g  = (const float*)d_in[7];
    const float* k_b  = (const float*)d_in[8];
    const float* k_m  = (const float*)d_in[9];
    const float* k_v  = (const float*)d_in[10];
    const float* v_w  = (const float*)d_in[11];
    const float* v_g  = (const float*)d_in[12];
    const float* v_b  = (const float*)d_in[13];
    const float* v_m  = (const float*)d_in[14];
    const float* v_v  = (const float*)d_in[15];
    const float* p_w  = (const float*)d_in[16];
    const float* p_b  = (const float*)d_in[17];
    const float* p_g  = (const float*)d_in[18];
    const float* p_b2 = (const float*)d_in[19];
    const float* p_m  = (const float*)d_in[20];
    const float* p_v  = (const float*)d_in[21];
    float* out = (float*)d_out;

    cudaFuncSetAttribute(gemm_kernel<0>, cudaFuncAttributeMaxDynamicSharedMemorySize, SMEM_BYTES);
    cudaFuncSetAttribute(gemm_kernel<1>, cudaFuncAttributeMaxDynamicSharedMemorySize, SMEM_BYTES);

    prep_kernel<<<(C_ * C_ + 255) / 256, 256>>>(
        q_w, q_g, q_b, q_m, q_v,
        k_w, k_g, k_b, k_m, k_v,
        v_w, v_g, v_b, v_m, v_v,
        p_w, p_b, p_g, p_b2, p_m, p_v);

    lif_x_kernel<<<(S_ / 4 + 255) / 256, 256>>>(reinterpret_cast<const float4*>(x));

    // MODE 0: q/k/v convs (raw pre-activations)
    gemm_kernel<0><<<dim3(N_ / BN, C_ / BM, 3 * T_ * B_), 128, SMEM_BYTES>>>(nullptr, nullptr);

    // BN shift + LIF -> binary spikes in place
    lif_qkv_kernel<<<dim3((S_ / 4 + 255) / 256, 3), 256>>>();

    kv_kernel<<<(B_ * C_ * 32 + 255) / 256, 256>>>();

    // MODE 1: proj conv on q*kvs + BN + bias + identity
    gemm_kernel<1><<<dim3(N_ / BN, C_ / BM, T_ * B_), 128, SMEM_BYTES>>>(x, out);
}

// round 10
// speedup vs baseline: 4.2549x; 3.0701x over previous
#include <cuda_runtime.h>
#include <cuda_fp16.h>
#include <mma.h>

using namespace nvcuda;

// Problem constants
constexpr int T_ = 4;
constexpr int B_ = 16;
constexpr int C_ = 512;
constexpr int N_ = 256;                // H*W
constexpr int S_ = B_ * C_ * N_;       // per-timestep elements
constexpr int TOT_ = T_ * S_;

// GEMM tiling: block 128x128x32, 4 warps, warp tile 64x64, fp16 operands
constexpr int BM = 128, BN = 128, BK = 32;
constexpr int ASTRH = 40;    // half stride; 80B = 5*16
constexpr int BSTRH = 136;   // 272B = 17*16
constexpr int CSTR = 132;    // float stride for epilogue staging; 528B = 33*16
constexpr int PIPE_BYTES = 2 * (BM * ASTRH + BK * BSTRH) * 2;   // 37888
constexpr int EPI_BYTES = BM * CSTR * 4;                        // 67584
constexpr int SMEM_BYTES = (PIPE_BYTES > EPI_BYTES) ? PIPE_BYTES : EPI_BYTES;

// Scratch (device globals: allocation-free rule)
__device__ __align__(16) __half g_wq[C_ * C_];
__device__ __align__(16) __half g_wk[C_ * C_];
__device__ __align__(16) __half g_wv[C_ * C_];
__device__ __align__(16) __half g_wp[C_ * C_];
__device__ float g_sq[C_];
__device__ float g_sk[C_];
__device__ float g_sv[C_];
__device__ float g_sp[C_];
__device__ __align__(16) __half g_xs[TOT_];          // input spikes
__device__ __align__(16) float g_q[TOT_];            // q pre-activations (fp32)
__device__ __align__(16) float g_k[TOT_];
__device__ __align__(16) float g_v[TOT_];
__device__ __align__(16) __half g_qs[TOT_];          // q/k/v spikes (fp16)
__device__ __align__(16) __half g_ks[TOT_];
__device__ __align__(16) __half g_vs[TOT_];
__device__ float g_kvs[T_ * B_ * C_];

// ---------------------------------------------------------------------------
// cp.async helpers
// ---------------------------------------------------------------------------
__device__ __forceinline__ void cp16(void* dst, const void* src) {
    unsigned s = (unsigned)__cvta_generic_to_shared(dst);
    asm volatile("cp.async.cg.shared.global [%0], [%1], 16;\n" :: "r"(s), "l"(src));
}
__device__ __forceinline__ void cp16p(void* dst, const void* src, int srcsize) {
    unsigned s = (unsigned)__cvta_generic_to_shared(dst);
    asm volatile("cp.async.cg.shared.global [%0], [%1], 16, %2;\n" :: "r"(s), "l"(src), "r"(srcsize));
}
#define CP_COMMIT() asm volatile("cp.async.commit_group;\n" ::: "memory")
#define CP_WAIT0()  asm volatile("cp.async.wait_group 0;\n" ::: "memory")

// ---------------------------------------------------------------------------
// Prep: fold BN scale into weights (fp16); per-channel shifts (fp32).
// ---------------------------------------------------------------------------
__global__ void prep_kernel(
    const float* __restrict__ qw, const float* __restrict__ qg, const float* __restrict__ qb,
    const float* __restrict__ qm, const float* __restrict__ qvv,
    const float* __restrict__ kw, const float* __restrict__ kg, const float* __restrict__ kb,
    const float* __restrict__ km, const float* __restrict__ kvv,
    const float* __restrict__ vw, const float* __restrict__ vg, const float* __restrict__ vb,
    const float* __restrict__ vm, const float* __restrict__ vvv,
    const float* __restrict__ pw, const float* __restrict__ pb, const float* __restrict__ pg,
    const float* __restrict__ pb2, const float* __restrict__ pm, const float* __restrict__ pvv)
{
    int idx = blockIdx.x * blockDim.x + threadIdx.x;
    if (idx >= C_ * C_) return;
    int o = idx >> 9;
    float invq = qg[o] / sqrtf(qvv[o] + 1e-5f);
    float invk = kg[o] / sqrtf(kvv[o] + 1e-5f);
    float invv = vg[o] / sqrtf(vvv[o] + 1e-5f);
    float invp = pg[o] / sqrtf(pvv[o] + 1e-5f);
    g_wq[idx] = __float2half_rn(qw[idx] * invq);
    g_wk[idx] = __float2half_rn(kw[idx] * invk);
    g_wv[idx] = __float2half_rn(vw[idx] * invv);
    g_wp[idx] = __float2half_rn(pw[idx] * invp);
    if ((idx & 511) == 0) {
        g_sq[o] = qb[o] - qm[o] * invq;
        g_sk[o] = kb[o] - km[o] * invk;
        g_sv[o] = vb[o] - vm[o] * invv;
        g_sp[o] = (pb[o] - pm[o]) * invp + pb2[o];
    }
}

// ---------------------------------------------------------------------------
// LIF on input x -> binary spikes xs (half). 4 elems/thread.
// ---------------------------------------------------------------------------
__global__ void lif_x_kernel(const float4* __restrict__ x4)
{
    int i = blockIdx.x * blockDim.x + threadIdx.x;
    if (i >= S_ / 4) return;
    float4 v = make_float4(0.f, 0.f, 0.f, 0.f);
#pragma unroll
    for (int t = 0; t < T_; t++) {
        float4 xv = x4[t * (S_ / 4) + i];
        float4 s;
        v.x += (xv.x - v.x) * 0.5f; s.x = (v.x >= 1.f) ? 1.f : 0.f; v.x *= (1.f - s.x);
        v.y += (xv.y - v.y) * 0.5f; s.y = (v.y >= 1.f) ? 1.f : 0.f; v.y *= (1.f - s.y);
        v.z += (xv.z - v.z) * 0.5f; s.z = (v.z >= 1.f) ? 1.f : 0.f; v.z *= (1.f - s.z);
        v.w += (xv.w - v.w) * 0.5f; s.w = (v.w >= 1.f) ? 1.f : 0.f; v.w *= (1.f - s.w);
        __half2* o2 = reinterpret_cast<__half2*>(g_xs + t * S_) + 2 * i;
        o2[0] = __floats2half2_rn(s.x, s.y);
        o2[1] = __floats2half2_rn(s.z, s.w);
    }
}

// ---------------------------------------------------------------------------
// LIF on q/k/v fp32 pre-activations (+ BN shift) -> half spikes.
// ---------------------------------------------------------------------------
__global__ void lif_qkv_kernel()
{
    int i = blockIdx.x * blockDim.x + threadIdx.x;
    if (i >= S_ / 4) return;
    int which = blockIdx.y;
    const float4* buf = reinterpret_cast<const float4*>((which == 0) ? g_q : (which == 1) ? g_k : g_v);
    __half* dst = (which == 0) ? g_qs : (which == 1) ? g_ks : g_vs;
    const float* sh = (which == 0) ? g_sq : (which == 1) ? g_sk : g_sv;
    int c = (i >> 6) & (C_ - 1);    // i indexes [b][c][n/4], 64 float4 per row
    float shift = __ldg(&sh[c]);
    float4 v = make_float4(0.f, 0.f, 0.f, 0.f);
#pragma unroll
    for (int t = 0; t < T_; t++) {
        float4 p = buf[t * (S_ / 4) + i];
        p.x += shift; p.y += shift; p.z += shift; p.w += shift;
        float4 s;
        v.x += (p.x - v.x) * 0.5f; s.x = (v.x >= 1.f) ? 1.f : 0.f; v.x *= (1.f - s.x);
        v.y += (p.y - v.y) * 0.5f; s.y = (v.y >= 1.f) ? 1.f : 0.f; v.y *= (1.f - s.y);
        v.z += (p.z - v.z) * 0.5f; s.z = (v.z >= 1.f) ? 1.f : 0.f; v.z *= (1.f - s.z);
        v.w += (p.w - v.w) * 0.5f; s.w = (v.w >= 1.f) ? 1.f : 0.f; v.w *= (1.f - s.w);
        __half2* o2 = reinterpret_cast<__half2*>(dst + t * S_) + 2 * i;
        o2[0] = __floats2half2_rn(s.x, s.y);
        o2[1] = __floats2half2_rn(s.z, s.w);
    }
}

// ---------------------------------------------------------------------------
// kv = sum_n k*v per (t,b,c) (half spikes, exact), then LIF v_th=0.5.
// One warp per (b,c); one uint4 (8 halfs) per lane covers the 256-row.
// ---------------------------------------------------------------------------
__global__ void kv_kernel()
{
    int gw = (blockIdx.x * blockDim.x + threadIdx.x) >> 5;
    int lane = threadIdx.x & 31;
    if (gw >= B_ * C_) return;      // gw = b*C + c
    float v = 0.f;
#pragma unroll
    for (int t = 0; t < T_; t++) {
        const uint4* kp = reinterpret_cast<const uint4*>(g_ks + t * S_ + gw * N_);
        const uint4* vp = reinterpret_cast<const uint4*>(g_vs + t * S_ + gw * N_);
        uint4 a = kp[lane];
        uint4 b = vp[lane];
        const __half2* ah = reinterpret_cast<const __half2*>(&a);
        const __half2* bh = reinterpret_cast<const __half2*>(&b);
        float sum = 0.f;
#pragma unroll
        for (int m = 0; m < 4; m++) {
            float2 f = __half22float2(__hmul2(ah[m], bh[m]));
            sum += f.x + f.y;
        }
#pragma unroll
        for (int off = 16; off > 0; off >>= 1)
            sum += __shfl_xor_sync(0xFFFFFFFFu, sum, off);
        v = v + (sum - v) * 0.5f;
        float s = (v >= 0.5f) ? 1.f : 0.f;
        if (lane == 0) g_kvs[t * B_ * C_ + gw] = s;
        v = v * (1.f - s);
    }
}

// ---------------------------------------------------------------------------
// fp16 GEMM (fp32 accumulate), block 128x128x32, 4 warps (64x64 warp tile),
// 2-stage cp.async.
// MODE 0: z = which*64 + tb.  A = folded fp16 weights, B = xs spikes,
//         writes fp32 pre-activations to g_q/g_k/g_v.
// MODE 1: z = tb. A = proj weights, B = q spikes gated by kvs (zero-fill
//         cp.async); epilogue adds shift + identity, writes d_out.
// ---------------------------------------------------------------------------
template <int MODE>
__global__ void __launch_bounds__(128) gemm_kernel(const float* __restrict__ x_identity,
                                                   float* __restrict__ out_global)
{
    extern __shared__ __align__(16) char smemc[];
    __half* AsBase = reinterpret_cast<__half*>(smemc);              // [2][BM*ASTRH]
    __half* BsBase = AsBase + 2 * BM * ASTRH;                       // [2][BK*BSTRH]
    float* Cs = reinterpret_cast<float*>(smemc);                    // overlaps (after sync)

    int tid = threadIdx.x;
    int warp = tid >> 5;
    int wr = warp >> 1, wc = warp & 1;         // warp tile origin: (wr*64, wc*64)
    int n0 = blockIdx.x * BN;
    int o0 = blockIdx.y * BM;
    int z = blockIdx.z;

    const __half* A;
    const __half* Bsrc;
    float* Cdst = nullptr;
    const float* kvs = nullptr;
    const float* xid = nullptr;
    float* outp = nullptr;
    const float* shp = nullptr;

    if (MODE == 0) {
        int which = z >> 6;
        int tb = z & 63;
        A = (which == 0) ? g_wq : (which == 1) ? g_wk : g_wv;
        Bsrc = g_xs + (size_t)tb * C_ * N_;
        Cdst = ((which == 0) ? g_q : (which == 1) ? g_k : g_v) + (size_t)tb * C_ * N_;
    } else {
        A = g_wp;
        shp = g_sp;
        Bsrc = g_qs + (size_t)z * C_ * N_;
        kvs = g_kvs + z * C_;
        xid = x_identity + (size_t)z * C_ * N_;
        outp = out_global + (size_t)z * C_ * N_;
    }

    wmma::fragment<wmma::accumulator, 16, 16, 16, float> acc[4][4];
#pragma unroll
    for (int i = 0; i < 4; i++)
#pragma unroll
        for (int j = 0; j < 4; j++)
            wmma::fill_fragment(acc[i][j], 0.0f);

    // A: 128 rows x 32 halfs = 4 chunks/row -> 512 chunks, 4/thread
    // B: 32 rows x 128 halfs = 16 chunks/row -> 512 chunks, 4/thread
    // ---- prologue
    {
        __half* As = AsBase;
        __half* Bs = BsBase;
#pragma unroll
        for (int i = 0; i < 4; i++) {
            int idx = tid + i * 128;
            int r = idx >> 2, c8 = (idx & 3) << 3;
            cp16(&As[r * ASTRH + c8], &A[(o0 + r) * C_ + c8]);
        }
#pragma unroll
        for (int i = 0; i < 4; i++) {
            int idx = tid + i * 128;
            int r = idx >> 4, c8 = (idx & 15) << 3;
            if (MODE == 0) {
                cp16(&Bs[r * BSTRH + c8], &Bsrc[r * N_ + n0 + c8]);
            } else {
                int sz = (__ldg(&kvs[r]) != 0.f) ? 16 : 0;
                cp16p(&Bs[r * BSTRH + c8], &Bsrc[r * N_ + n0 + c8], sz);
            }
        }
        CP_COMMIT();
    }

    // ---- main K loop
    int s = 0;
    for (int kt = 0; kt < C_; kt += BK, s ^= 1) {
        CP_WAIT0();
        __syncthreads();

        if (kt + BK < C_) {
            __half* As = AsBase + (s ^ 1) * BM * ASTRH;
            __half* Bs = BsBase + (s ^ 1) * BK * BSTRH;
            int ktn = kt + BK;
#pragma unroll
            for (int i = 0; i < 4; i++) {
                int idx = tid + i * 128;
                int r = idx >> 2, c8 = (idx & 3) << 3;
                cp16(&As[r * ASTRH + c8], &A[(o0 + r) * C_ + ktn + c8]);
            }
#pragma unroll
            for (int i = 0; i < 4; i++) {
                int idx = tid + i * 128;
                int r = idx >> 4, c8 = (idx & 15) << 3;
                if (MODE == 0) {
                    cp16(&Bs[r * BSTRH + c8], &Bsrc[(ktn + r) * N_ + n0 + c8]);
                } else {
                    int sz = (__ldg(&kvs[ktn + r]) != 0.f) ? 16 : 0;
                    cp16p(&Bs[r * BSTRH + c8], &Bsrc[(ktn + r) * N_ + n0 + c8], sz);
                }
            }
            CP_COMMIT();
        }

        const __half* As = AsBase + s * BM * ASTRH;
        const __half* Bs = BsBase + s * BK * BSTRH;
#pragma unroll
        for (int kk = 0; kk < BK; kk += 16) {
            wmma::fragment<wmma::matrix_a, 16, 16, 16, __half, wmma::row_major> af[4];
            wmma::fragment<wmma::matrix_b, 16, 16, 16, __half, wmma::row_major> bf[4];
#pragma unroll
            for (int i = 0; i < 4; i++)
                wmma::load_matrix_sync(af[i], &As[(wr * 64 + i * 16) * ASTRH + kk], ASTRH);
#pragma unroll
            for (int j = 0; j < 4; j++)
                wmma::load_matrix_sync(bf[j], &Bs[kk * BSTRH + wc * 64 + j * 16], BSTRH);
#pragma unroll
            for (int i = 0; i < 4; i++)
#pragma unroll
                for (int j = 0; j < 4; j++)
                    wmma::mma_sync(acc[i][j], af[i], bf[j], acc[i][j]);
        }
    }

    // ---- epilogue: stage through smem (fp32) for coalesced float4 stores
    __syncthreads();
#pragma unroll
    for (int i = 0; i < 4; i++)
#pragma unroll
        for (int j = 0; j < 4; j++)
            wmma::store_matrix_sync(&Cs[(wr * 64 + i * 16) * CSTR + wc * 64 + j * 16],
                                    acc[i][j], CSTR, wmma::mem_row_major);
    __syncthreads();

    // 128x128 tile = 4096 float4; 32 per thread
    if (MODE == 0) {
#pragma unroll
        for (int e = 0; e < 32; e++) {
            int idx = tid + e * 128;
            int r = idx >> 5, c4 = (idx & 31) << 2;
            float4 cv = *reinterpret_cast<const float4*>(&Cs[r * CSTR + c4]);
            *reinterpret_cast<float4*>(&Cdst[(o0 + r) * N_ + n0 + c4]) = cv;
        }
    } else {
#pragma unroll
        for (int e = 0; e < 32; e++) {
            int idx = tid + e * 128;
            int r = idx >> 5, c4 = (idx & 31) << 2;
            int o = o0 + r;
            float4 cv = *reinterpret_cast<const float4*>(&Cs[r * CSTR + c4]);
            float4 xv = *reinterpret_cast<const float4*>(&xid[o * N_ + n0 + c4]);
            float sp = __ldg(&shp[o]);
            float4 res;
            res.x = cv.x + sp + xv.x;
            res.y = cv.y + sp + xv.y;
            res.z = cv.z + sp + xv.z;
            res.w = cv.w + sp + xv.w;
            *reinterpret_cast<float4*>(&outp[o * N_ + n0 + c4]) = res;
        }
    }
}

// ---------------------------------------------------------------------------
extern "C" void kernel_launch(void* const* d_in, const int* in_sizes, int n_in,
                              void* d_out, int out_size)
{
    const float* x    = (const float*)d_in[0];
    const float* q_w  = (const float*)d_in[1];
    const float* q_g  = (const float*)d_in[2];
    const float* q_b  = (const float*)d_in[3];
    const float* q_m  = (const float*)d_in[4];
    const float* q_v  = (const float*)d_in[5];
    const float* k_w  = (const float*)d_in[6];
    const float* k_g  = (const float*)d_in[7];
    const float* k_b  = (const float*)d_in[8];
    const float* k_m  = (const float*)d_in[9];
    const float* k_v  = (const float*)d_in[10];
    const float* v_w  = (const float*)d_in[11];
    const float* v_g  = (const float*)d_in[12];
    const float* v_b  = (const float*)d_in[13];
    const float* v_m  = (const float*)d_in[14];
    const float* v_v  = (const float*)d_in[15];
    const float* p_w  = (const float*)d_in[16];
    const float* p_b  = (const float*)d_in[17];
    const float* p_g  = (const float*)d_in[18];
    const float* p_b2 = (const float*)d_in[19];
    const float* p_m  = (const float*)d_in[20];
    const float* p_v  = (const float*)d_in[21];
    float* out = (float*)d_out;

    cudaFuncSetAttribute(gemm_kernel<0>, cudaFuncAttributeMaxDynamicSharedMemorySize, SMEM_BYTES);
    cudaFuncSetAttribute(gemm_kernel<1>, cudaFuncAttributeMaxDynamicSharedMemorySize, SMEM_BYTES);

    prep_kernel<<<(C_ * C_ + 255) / 256, 256>>>(
        q_w, q_g, q_b, q_m, q_v,
        k_w, k_g, k_b, k_m, k_v,
        v_w, v_g, v_b, v_m, v_v,
        p_w, p_b, p_g, p_b2, p_m, p_v);

    lif_x_kernel<<<(S_ / 4 + 255) / 256, 256>>>(reinterpret_cast<const float4*>(x));

    // MODE 0: q/k/v convs (fp32 pre-activations)
    gemm_kernel<0><<<dim3(N_ / BN, C_ / BM, 3 * T_ * B_), 128, SMEM_BYTES>>>(nullptr, nullptr);

    // BN shift + LIF -> half spikes
    lif_qkv_kernel<<<dim3((S_ / 4 + 255) / 256, 3), 256>>>();

    kv_kernel<<<(B_ * C_ * 32 + 255) / 256, 256>>>();

    // MODE 1: proj conv on q*kvs + BN + bias + identity
    gemm_kernel<1><<<dim3(N_ / BN, C_ / BM, T_ * B_), 128, SMEM_BYTES>>>(x, out);
}

// round 11
// speedup vs baseline: 4.7028x; 1.1053x over previous
#include <cuda_runtime.h>
#include <cuda_fp16.h>
#include <mma.h>

using namespace nvcuda;

// Problem constants
constexpr int T_ = 4;
constexpr int B_ = 16;
constexpr int C_ = 512;
constexpr int N_ = 256;                // H*W
constexpr int S_ = B_ * C_ * N_;       // per-timestep elements
constexpr int TOT_ = T_ * S_;

// GEMM tiling: block 128x128x32, 4 warps, warp tile 64x64, fp16 operands
constexpr int BM = 128, BN = 128, BK = 32;
constexpr int ASTRH = 40;    // half stride; 80B = 5*16
constexpr int BSTRH = 136;   // 272B = 17*16
constexpr int CSTR = 132;    // float stride for epilogue staging; 528B = 33*16
constexpr int PIPE_BYTES = 2 * (BM * ASTRH + BK * BSTRH) * 2;   // 37888
constexpr int EPI_BYTES = BM * CSTR * 4;                        // 67584
constexpr int SMEM_BYTES = (PIPE_BYTES > EPI_BYTES) ? PIPE_BYTES : EPI_BYTES;

// Scratch (device globals: allocation-free rule)
__device__ __align__(16) __half g_wq[C_ * C_];
__device__ __align__(16) __half g_wk[C_ * C_];
__device__ __align__(16) __half g_wv[C_ * C_];
__device__ __align__(16) __half g_wp[C_ * C_];
__device__ float g_sq[C_];
__device__ float g_sk[C_];
__device__ float g_sv[C_];
__device__ float g_sp[C_];
__device__ __align__(16) __half g_xs[TOT_];          // input spikes
__device__ __align__(16) float g_q[TOT_];            // q pre-activations (fp32)
__device__ __align__(16) float g_k[TOT_];
__device__ __align__(16) float g_v[TOT_];
__device__ __align__(16) __half g_attn[TOT_];        // attn = q_spike * kv_spike (fp16)

// ---------------------------------------------------------------------------
// cp.async helpers
// ---------------------------------------------------------------------------
__device__ __forceinline__ void cp16(void* dst, const void* src) {
    unsigned s = (unsigned)__cvta_generic_to_shared(dst);
    asm volatile("cp.async.cg.shared.global [%0], [%1], 16;\n" :: "r"(s), "l"(src));
}
#define CP_COMMIT() asm volatile("cp.async.commit_group;\n" ::: "memory")
#define CP_WAIT0()  asm volatile("cp.async.wait_group 0;\n" ::: "memory")

// ---------------------------------------------------------------------------
// Prep: fold BN scale into weights (fp16); per-channel shifts (fp32).
// ---------------------------------------------------------------------------
__global__ void prep_kernel(
    const float* __restrict__ qw, const float* __restrict__ qg, const float* __restrict__ qb,
    const float* __restrict__ qm, const float* __restrict__ qvv,
    const float* __restrict__ kw, const float* __restrict__ kg, const float* __restrict__ kb,
    const float* __restrict__ km, const float* __restrict__ kvv,
    const float* __restrict__ vw, const float* __restrict__ vg, const float* __restrict__ vb,
    const float* __restrict__ vm, const float* __restrict__ vvv,
    const float* __restrict__ pw, const float* __restrict__ pb, const float* __restrict__ pg,
    const float* __restrict__ pb2, const float* __restrict__ pm, const float* __restrict__ pvv)
{
    int idx = blockIdx.x * blockDim.x + threadIdx.x;
    if (idx >= C_ * C_) return;
    int o = idx >> 9;
    float invq = qg[o] / sqrtf(qvv[o] + 1e-5f);
    float invk = kg[o] / sqrtf(kvv[o] + 1e-5f);
    float invv = vg[o] / sqrtf(vvv[o] + 1e-5f);
    float invp = pg[o] / sqrtf(pvv[o] + 1e-5f);
    g_wq[idx] = __float2half_rn(qw[idx] * invq);
    g_wk[idx] = __float2half_rn(kw[idx] * invk);
    g_wv[idx] = __float2half_rn(vw[idx] * invv);
    g_wp[idx] = __float2half_rn(pw[idx] * invp);
    if ((idx & 511) == 0) {
        g_sq[o] = qb[o] - qm[o] * invq;
        g_sk[o] = kb[o] - km[o] * invk;
        g_sv[o] = vb[o] - vm[o] * invv;
        g_sp[o] = (pb[o] - pm[o]) * invp + pb2[o];
    }
}

// ---------------------------------------------------------------------------
// LIF on input x -> binary spikes xs (half). 4 elems/thread.
// ---------------------------------------------------------------------------
__global__ void lif_x_kernel(const float4* __restrict__ x4)
{
    int i = blockIdx.x * blockDim.x + threadIdx.x;
    if (i >= S_ / 4) return;
    float4 v = make_float4(0.f, 0.f, 0.f, 0.f);
#pragma unroll
    for (int t = 0; t < T_; t++) {
        float4 xv = x4[t * (S_ / 4) + i];
        float4 s;
        v.x += (xv.x - v.x) * 0.5f; s.x = (v.x >= 1.f) ? 1.f : 0.f; v.x *= (1.f - s.x);
        v.y += (xv.y - v.y) * 0.5f; s.y = (v.y >= 1.f) ? 1.f : 0.f; v.y *= (1.f - s.y);
        v.z += (xv.z - v.z) * 0.5f; s.z = (v.z >= 1.f) ? 1.f : 0.f; v.z *= (1.f - s.z);
        v.w += (xv.w - v.w) * 0.5f; s.w = (v.w >= 1.f) ? 1.f : 0.f; v.w *= (1.f - s.w);
        __half2* o2 = reinterpret_cast<__half2*>(g_xs + t * S_) + 2 * i;
        o2[0] = __floats2half2_rn(s.x, s.y);
        o2[1] = __floats2half2_rn(s.z, s.w);
    }
}

// ---------------------------------------------------------------------------
// Fused: LIF(q/k/v pre-act + BN shift) -> kv row-sum -> kv-LIF (v_th=0.5)
//        -> attn = q_spike * kv_spike, written as fp16.
// One warp per (b,c) row; 8 elements per lane; t sequential in registers.
// k/v/q spike tensors never touch DRAM.
// ---------------------------------------------------------------------------
__global__ void lif_attn_kernel()
{
    int gw = (blockIdx.x * blockDim.x + threadIdx.x) >> 5;   // b*C + c
    int lane = threadIdx.x & 31;
    if (gw >= B_ * C_) return;
    int c = gw & (C_ - 1);
    float shq = __ldg(&g_sq[c]);
    float shk = __ldg(&g_sk[c]);
    float shv = __ldg(&g_sv[c]);

    float vq[8], vk[8], vv[8];
#pragma unroll
    for (int e = 0; e < 8; e++) { vq[e] = 0.f; vk[e] = 0.f; vv[e] = 0.f; }
    float vkv = 0.f;

#pragma unroll
    for (int t = 0; t < T_; t++) {
        size_t base = (size_t)t * S_ + (size_t)gw * N_ + lane * 8;
        float4 q0 = *reinterpret_cast<const float4*>(g_q + base);
        float4 q1 = *reinterpret_cast<const float4*>(g_q + base + 4);
        float4 k0 = *reinterpret_cast<const float4*>(g_k + base);
        float4 k1 = *reinterpret_cast<const float4*>(g_k + base + 4);
        float4 v0 = *reinterpret_cast<const float4*>(g_v + base);
        float4 v1 = *reinterpret_cast<const float4*>(g_v + base + 4);
        float qp[8] = {q0.x, q0.y, q0.z, q0.w, q1.x, q1.y, q1.z, q1.w};
        float kp[8] = {k0.x, k0.y, k0.z, k0.w, k1.x, k1.y, k1.z, k1.w};
        float vp[8] = {v0.x, v0.y, v0.z, v0.w, v1.x, v1.y, v1.z, v1.w};

        float sq[8], sk[8], sv[8];
        float kvsum = 0.f;
#pragma unroll
        for (int e = 0; e < 8; e++) {
            float p;
            p = qp[e] + shq;
            vq[e] += (p - vq[e]) * 0.5f; sq[e] = (vq[e] >= 1.f) ? 1.f : 0.f; vq[e] *= (1.f - sq[e]);
            p = kp[e] + shk;
            vk[e] += (p - vk[e]) * 0.5f; sk[e] = (vk[e] >= 1.f) ? 1.f : 0.f; vk[e] *= (1.f - sk[e]);
            p = vp[e] + shv;
            vv[e] += (p - vv[e]) * 0.5f; sv[e] = (vv[e] >= 1.f) ? 1.f : 0.f; vv[e] *= (1.f - sv[e]);
            kvsum += sk[e] * sv[e];
        }
#pragma unroll
        for (int off = 16; off > 0; off >>= 1)
            kvsum += __shfl_xor_sync(0xFFFFFFFFu, kvsum, off);

        // kv LIF (all lanes compute identically)
        vkv = vkv + (kvsum - vkv) * 0.5f;
        float skv = (vkv >= 0.5f) ? 1.f : 0.f;
        vkv = vkv * (1.f - skv);

        // attn = q_spike * kv_spike -> fp16 (exact 0/1)
        uint4 pk;
        __half2* ph = reinterpret_cast<__half2*>(&pk);
        ph[0] = __floats2half2_rn(sq[0] * skv, sq[1] * skv);
        ph[1] = __floats2half2_rn(sq[2] * skv, sq[3] * skv);
        ph[2] = __floats2half2_rn(sq[4] * skv, sq[5] * skv);
        ph[3] = __floats2half2_rn(sq[6] * skv, sq[7] * skv);
        *reinterpret_cast<uint4*>(g_attn + base) = pk;
    }
}

// ---------------------------------------------------------------------------
// fp16 GEMM (fp32 accumulate), block 128x128x32, 4 warps (64x64 warp tile),
// 2-stage cp.async.
// MODE 0: z = which*64 + tb.  A = folded fp16 weights, B = xs spikes,
//         writes fp32 pre-activations to g_q/g_k/g_v.
// MODE 1: z = tb. A = proj weights, B = attn (precomputed q*kvs spikes);
//         epilogue adds shift + identity, writes d_out.
// ---------------------------------------------------------------------------
template <int MODE>
__global__ void __launch_bounds__(128) gemm_kernel(const float* __restrict__ x_identity,
                                                   float* __restrict__ out_global)
{
    extern __shared__ __align__(16) char smemc[];
    __half* AsBase = reinterpret_cast<__half*>(smemc);              // [2][BM*ASTRH]
    __half* BsBase = AsBase + 2 * BM * ASTRH;                       // [2][BK*BSTRH]
    float* Cs = reinterpret_cast<float*>(smemc);                    // overlaps (after sync)

    int tid = threadIdx.x;
    int warp = tid >> 5;
    int wr = warp >> 1, wc = warp & 1;         // warp tile origin: (wr*64, wc*64)
    int n0 = blockIdx.x * BN;
    int o0 = blockIdx.y * BM;
    int z = blockIdx.z;

    const __half* A;
    const __half* Bsrc;
    float* Cdst = nullptr;
    const float* xid = nullptr;
    float* outp = nullptr;
    const float* shp = nullptr;

    if (MODE == 0) {
        int which = z >> 6;
        int tb = z & 63;
        A = (which == 0) ? g_wq : (which == 1) ? g_wk : g_wv;
        Bsrc = g_xs + (size_t)tb * C_ * N_;
        Cdst = ((which == 0) ? g_q : (which == 1) ? g_k : g_v) + (size_t)tb * C_ * N_;
    } else {
        A = g_wp;
        shp = g_sp;
        Bsrc = g_attn + (size_t)z * C_ * N_;
        xid = x_identity + (size_t)z * C_ * N_;
        outp = out_global + (size_t)z * C_ * N_;
    }

    wmma::fragment<wmma::accumulator, 16, 16, 16, float> acc[4][4];
#pragma unroll
    for (int i = 0; i < 4; i++)
#pragma unroll
        for (int j = 0; j < 4; j++)
            wmma::fill_fragment(acc[i][j], 0.0f);

    // A: 128 rows x 32 halfs = 4 chunks/row -> 512 chunks, 4/thread
    // B: 32 rows x 128 halfs = 16 chunks/row -> 512 chunks, 4/thread
    // ---- prologue
    {
        __half* As = AsBase;
        __half* Bs = BsBase;
#pragma unroll
        for (int i = 0; i < 4; i++) {
            int idx = tid + i * 128;
            int r = idx >> 2, c8 = (idx & 3) << 3;
            cp16(&As[r * ASTRH + c8], &A[(o0 + r) * C_ + c8]);
        }
#pragma unroll
        for (int i = 0; i < 4; i++) {
            int idx = tid + i * 128;
            int r = idx >> 4, c8 = (idx & 15) << 3;
            cp16(&Bs[r * BSTRH + c8], &Bsrc[r * N_ + n0 + c8]);
        }
        CP_COMMIT();
    }

    // ---- main K loop
    int s = 0;
    for (int kt = 0; kt < C_; kt += BK, s ^= 1) {
        CP_WAIT0();
        __syncthreads();

        if (kt + BK < C_) {
            __half* As = AsBase + (s ^ 1) * BM * ASTRH;
            __half* Bs = BsBase + (s ^ 1) * BK * BSTRH;
            int ktn = kt + BK;
#pragma unroll
            for (int i = 0; i < 4; i++) {
                int idx = tid + i * 128;
                int r = idx >> 2, c8 = (idx & 3) << 3;
                cp16(&As[r * ASTRH + c8], &A[(o0 + r) * C_ + ktn + c8]);
            }
#pragma unroll
            for (int i = 0; i < 4; i++) {
                int idx = tid + i * 128;
                int r = idx >> 4, c8 = (idx & 15) << 3;
                cp16(&Bs[r * BSTRH + c8], &Bsrc[(ktn + r) * N_ + n0 + c8]);
            }
            CP_COMMIT();
        }

        const __half* As = AsBase + s * BM * ASTRH;
        const __half* Bs = BsBase + s * BK * BSTRH;
#pragma unroll
        for (int kk = 0; kk < BK; kk += 16) {
            wmma::fragment<wmma::matrix_a, 16, 16, 16, __half, wmma::row_major> af[4];
            wmma::fragment<wmma::matrix_b, 16, 16, 16, __half, wmma::row_major> bf[4];
#pragma unroll
            for (int i = 0; i < 4; i++)
                wmma::load_matrix_sync(af[i], &As[(wr * 64 + i * 16) * ASTRH + kk], ASTRH);
#pragma unroll
            for (int j = 0; j < 4; j++)
                wmma::load_matrix_sync(bf[j], &Bs[kk * BSTRH + wc * 64 + j * 16], BSTRH);
#pragma unroll
            for (int i = 0; i < 4; i++)
#pragma unroll
                for (int j = 0; j < 4; j++)
                    wmma::mma_sync(acc[i][j], af[i], bf[j], acc[i][j]);
        }
    }

    // ---- epilogue: stage through smem (fp32) for coalesced float4 stores
    __syncthreads();
#pragma unroll
    for (int i = 0; i < 4; i++)
#pragma unroll
        for (int j = 0; j < 4; j++)
            wmma::store_matrix_sync(&Cs[(wr * 64 + i * 16) * CSTR + wc * 64 + j * 16],
                                    acc[i][j], CSTR, wmma::mem_row_major);
    __syncthreads();

    // 128x128 tile = 4096 float4; 32 per thread
    if (MODE == 0) {
#pragma unroll
        for (int e = 0; e < 32; e++) {
            int idx = tid + e * 128;
            int r = idx >> 5, c4 = (idx & 31) << 2;
            float4 cv = *reinterpret_cast<const float4*>(&Cs[r * CSTR + c4]);
            *reinterpret_cast<float4*>(&Cdst[(o0 + r) * N_ + n0 + c4]) = cv;
        }
    } else {
#pragma unroll
        for (int e = 0; e < 32; e++) {
            int idx = tid + e * 128;
            int r = idx >> 5, c4 = (idx & 31) << 2;
            int o = o0 + r;
            float4 cv = *reinterpret_cast<const float4*>(&Cs[r * CSTR + c4]);
            float4 xv = *reinterpret_cast<const float4*>(&xid[o * N_ + n0 + c4]);
            float sp = __ldg(&shp[o]);
            float4 res;
            res.x = cv.x + sp + xv.x;
            res.y = cv.y + sp + xv.y;
            res.z = cv.z + sp + xv.z;
            res.w = cv.w + sp + xv.w;
            *reinterpret_cast<float4*>(&outp[o * N_ + n0 + c4]) = res;
        }
    }
}

// ---------------------------------------------------------------------------
extern "C" void kernel_launch(void* const* d_in, const int* in_sizes, int n_in,
                              void* d_out, int out_size)
{
    const float* x    = (const float*)d_in[0];
    const float* q_w  = (const float*)d_in[1];
    const float* q_g  = (const float*)d_in[2];
    const float* q_b  = (const float*)d_in[3];
    const float* q_m  = (const float*)d_in[4];
    const float* q_v  = (const float*)d_in[5];
    const float* k_w  = (const float*)d_in[6];
    const float* k_g  = (const float*)d_in[7];
    const float* k_b  = (const float*)d_in[8];
    const float* k_m  = (const float*)d_in[9];
    const float* k_v  = (const float*)d_in[10];
    const float* v_w  = (const float*)d_in[11];
    const float* v_g  = (const float*)d_in[12];
    const float* v_b  = (const float*)d_in[13];
    const float* v_m  = (const float*)d_in[14];
    const float* v_v  = (const float*)d_in[15];
    const float* p_w  = (const float*)d_in[16];
    const float* p_b  = (const float*)d_in[17];
    const float* p_g  = (const float*)d_in[18];
    const float* p_b2 = (const float*)d_in[19];
    const float* p_m  = (const float*)d_in[20];
    const float* p_v  = (const float*)d_in[21];
    float* out = (float*)d_out;

    cudaFuncSetAttribute(gemm_kernel<0>, cudaFuncAttributeMaxDynamicSharedMemorySize, SMEM_BYTES);
    cudaFuncSetAttribute(gemm_kernel<1>, cudaFuncAttributeMaxDynamicSharedMemorySize, SMEM_BYTES);

    prep_kernel<<<(C_ * C_ + 255) / 256, 256>>>(
        q_w, q_g, q_b, q_m, q_v,
        k_w, k_g, k_b, k_m, k_v,
        v_w, v_g, v_b, v_m, v_v,
        p_w, p_b, p_g, p_b2, p_m, p_v);

    lif_x_kernel<<<(S_ / 4 + 255) / 256, 256>>>(reinterpret_cast<const float4*>(x));

    // MODE 0: q/k/v convs (fp32 pre-activations)
    gemm_kernel<0><<<dim3(N_ / BN, C_ / BM, 3 * T_ * B_), 128, SMEM_BYTES>>>(nullptr, nullptr);

    // Fused: LIF(q/k/v) + kv reduction + kv-LIF + attn gating -> g_attn (fp16)
    lif_attn_kernel<<<(B_ * C_ * 32 + 255) / 256, 256>>>();

    // MODE 1: proj conv on attn + BN + bias + identity
    gemm_kernel<1><<<dim3(N_ / BN, C_ / BM, T_ * B_), 128, SMEM_BYTES>>>(x, out);
}